// round 1
// baseline (speedup 1.0000x reference)
#include <cuda_runtime.h>
#include <cstdint>

#define F_IN   8192
#define F_OUT  16384
#define BATCH  32
#define HEADS  512

// Scratch (static __device__ — allocation-free per harness rules)
__device__ float g_xr[BATCH * F_IN];    // tf32-rounded x
__device__ float g_q[BATCH * F_OUT];
__device__ float g_k[BATCH * F_OUT];
__device__ float g_v[BATCH * F_OUT];
__device__ float g_rzt[BATCH * 32 * 32]; // 1/Z transposed: [b][j][i]

__device__ __forceinline__ uint32_t tf32_rna(float f) {
    uint32_t u;
    asm("cvt.rna.tf32.f32 %0, %1;" : "=r"(u) : "f"(f));
    return u;
}

__device__ __forceinline__ float gelu_exact(float v) {
    return 0.5f * v * (1.0f + erff(v * 0.70710678118654752f));
}

// ---------------------------------------------------------------------------
// Kernel 0: pre-round x to tf32 (RNA) once — avoids per-use cvt in the GEMM.
// ---------------------------------------------------------------------------
__global__ void round_x_kernel(const float* __restrict__ x) {
    int i = blockIdx.x * blockDim.x + threadIdx.x;
    int stride = gridDim.x * blockDim.x;
    for (; i < BATCH * F_IN; i += stride)
        g_xr[i] = __uint_as_float(tf32_rna(x[i]));
}

// ---------------------------------------------------------------------------
// Kernel 1: QKV GEMM. D[m,n] = gelu( sum_k x[m,k] * W[n,k] + b[n] )
// A = x (row-major), B = W (row-major == col-major K x N), tf32 mma.sync.
// CTA: 256 thr (8 warps), tile M=32 x N=128; warp tile M=32 x N=16.
// x streamed via cp.async double-buffered SMEM; W streamed direct GMEM->regs.
// ---------------------------------------------------------------------------
#define MMA_TF32(d, a0,a1,a2,a3, b0,b1)                                     \
    asm volatile("mma.sync.aligned.m16n8k8.row.col.f32.tf32.tf32.f32 "      \
        "{%0,%1,%2,%3}, {%4,%5,%6,%7}, {%8,%9}, {%0,%1,%2,%3};"             \
        : "+f"(d[0]), "+f"(d[1]), "+f"(d[2]), "+f"(d[3])                    \
        : "r"(a0), "r"(a1), "r"(a2), "r"(a3), "r"(b0), "r"(b1))

#define XS_STRIDE 132   // 128 + 4 pad: bank = 4*g + tq -> conflict-free

__global__ __launch_bounds__(256, 2)
void qkv_gemm_kernel(const float* __restrict__ Wq, const float* __restrict__ bq,
                     const float* __restrict__ Wk, const float* __restrict__ bk,
                     const float* __restrict__ Wv, const float* __restrict__ bv) {
    __shared__ float xs[2][32][XS_STRIDE];

    const float* W; const float* bias; float* out;
    if (blockIdx.y == 0)      { W = Wq; bias = bq; out = g_q; }
    else if (blockIdx.y == 1) { W = Wk; bias = bk; out = g_k; }
    else                      { W = Wv; bias = bv; out = g_v; }

    const int tid  = threadIdx.x;
    const int warp = tid >> 5;
    const int lane = tid & 31;
    const int g    = lane >> 2;   // groupID
    const int tq   = lane & 3;    // threadID_in_group
    const int nb   = blockIdx.x * 128 + warp * 16;

    const float* __restrict__ p0 = W + (size_t)(nb + g) * F_IN;       // n-tile 0 row
    const float* __restrict__ p1 = p0 + 8 * F_IN;                     // n-tile 1 row

    float acc[2][2][4];
    #pragma unroll
    for (int a = 0; a < 2; a++)
        #pragma unroll
        for (int b = 0; b < 2; b++)
            #pragma unroll
            for (int r = 0; r < 4; r++) acc[a][b][r] = 0.0f;

    // --- cp.async stage of one 32x128 x-chunk ---
    auto stage = [&](int buf, int kc) {
        #pragma unroll
        for (int r = 0; r < 4; r++) {
            int idx = tid + r * 256;              // 1024 float4 per chunk
            int m   = idx >> 5;
            int c4  = idx & 31;
            uint32_t dst = (uint32_t)__cvta_generic_to_shared(&xs[buf][m][c4 * 4]);
            const float* src = g_xr + (size_t)m * F_IN + kc + c4 * 4;
            asm volatile("cp.async.cg.shared.global [%0], [%1], 16;" :: "r"(dst), "l"(src));
        }
        asm volatile("cp.async.commit_group;");
    };

    stage(0, 0);

    for (int c = 0; c < 64; c++) {
        const int buf = c & 1;
        if (c < 63) {
            stage(buf ^ 1, (c + 1) * 128);
            asm volatile("cp.async.wait_group 1;");
        } else {
            asm volatile("cp.async.wait_group 0;");
        }
        __syncthreads();

        const float* xa  = &xs[buf][0][0] + g * XS_STRIDE + tq;
        const float* pb0 = p0 + c * 128 + tq;
        const float* pb1 = p1 + c * 128 + tq;

        #pragma unroll 8
        for (int s = 0; s < 16; s++) {
            const int kl = s * 8;
            // B fragments direct from GMEM (+RNA rounding to tf32)
            uint32_t B00 = tf32_rna(pb0[kl]);
            uint32_t B01 = tf32_rna(pb0[kl + 4]);
            uint32_t B10 = tf32_rna(pb1[kl]);
            uint32_t B11 = tf32_rna(pb1[kl + 4]);
            // A fragments from SMEM (already tf32-rounded)
            uint32_t A00 = __float_as_uint(xa[kl]);
            uint32_t A01 = __float_as_uint(xa[kl +  8 * XS_STRIDE]);
            uint32_t A02 = __float_as_uint(xa[kl + 4]);
            uint32_t A03 = __float_as_uint(xa[kl + 4 + 8 * XS_STRIDE]);
            uint32_t A10 = __float_as_uint(xa[kl + 16 * XS_STRIDE]);
            uint32_t A11 = __float_as_uint(xa[kl + 24 * XS_STRIDE]);
            uint32_t A12 = __float_as_uint(xa[kl + 4 + 16 * XS_STRIDE]);
            uint32_t A13 = __float_as_uint(xa[kl + 4 + 24 * XS_STRIDE]);

            MMA_TF32(acc[0][0], A00, A01, A02, A03, B00, B01);
            MMA_TF32(acc[0][1], A00, A01, A02, A03, B10, B11);
            MMA_TF32(acc[1][0], A10, A11, A12, A13, B00, B01);
            MMA_TF32(acc[1][1], A10, A11, A12, A13, B10, B11);
        }
        __syncthreads();
    }

    // Epilogue: bias + exact GELU, write qkv scratch
    #pragma unroll
    for (int mt = 0; mt < 2; mt++) {
        #pragma unroll
        for (int nt = 0; nt < 2; nt++) {
            const int row = mt * 16 + g;
            const int col = nb + nt * 8 + 2 * tq;
            const float2 bb = *reinterpret_cast<const float2*>(bias + col);
            float2 r0, r1;
            r0.x = gelu_exact(acc[mt][nt][0] + bb.x);
            r0.y = gelu_exact(acc[mt][nt][1] + bb.y);
            r1.x = gelu_exact(acc[mt][nt][2] + bb.x);
            r1.y = gelu_exact(acc[mt][nt][3] + bb.y);
            *reinterpret_cast<float2*>(out + (size_t)row * F_OUT + col)       = r0;
            *reinterpret_cast<float2*>(out + (size_t)(row + 8) * F_OUT + col) = r1;
        }
    }
}

// ---------------------------------------------------------------------------
// Kernel 2: softmax denominators over the HEADS axis.
// NOTE: bias[i,j] is constant along h => cancels in softmax. No max needed
// (|c*q*k| <= ~4.5, exp well within fp32 range).
// rZt[b][j][i] = 1 / sum_h exp(c * q[b,h,i] * k[b,h,j])
// Grid (32 b, 4 i-quarters), block 256: warp = local i, lanes = j.
// ---------------------------------------------------------------------------
#define ATTN_SCALE 0.17677669529663687f   // 1/sqrt(32)

__global__ void attn_z_kernel() {
    const int b  = blockIdx.x;
    const int iq = blockIdx.y;
    const int tid = threadIdx.x;
    const int il  = tid >> 5;      // warp id = local i (0..7)
    const int j   = tid & 31;
    const int i   = iq * 8 + il;

    __shared__ float qs[32][8];
    __shared__ float ks[32][32];

    const float* __restrict__ qb = g_q + (size_t)b * F_OUT;
    const float* __restrict__ kb = g_k + (size_t)b * F_OUT;

    float z = 0.0f;
    for (int hc = 0; hc < 16; hc++) {           // 16 chunks x 32 heads
        {
            int hh = tid >> 3, ii = tid & 7;
            qs[hh][ii] = qb[(size_t)(hc * 32 + hh) * 32 + iq * 8 + ii];
            #pragma unroll
            for (int r = 0; r < 4; r++) {
                int idx = tid + r * 256;
                int hh2 = idx >> 5, jj = idx & 31;
                ks[hh2][jj] = kb[(size_t)(hc * 32 + hh2) * 32 + jj];
            }
        }
        __syncthreads();
        #pragma unroll
        for (int hh = 0; hh < 32; hh++)
            z += __expf(ATTN_SCALE * qs[hh][il] * ks[hh][j]);
        __syncthreads();
    }
    g_rzt[(size_t)b * 1024 + j * 32 + i] = 1.0f / z;
}

// ---------------------------------------------------------------------------
// Kernel 3: out[b,h,i] = sum_j exp(c*q_i*k_j) * rZ[b,i,j] * v[b,h,j]
// Grid (64 h-chunks, 32 b), block 256: warp = h, lanes = i. k/v broadcast
// via register + shfl; rZt reads coalesced.
// ---------------------------------------------------------------------------
__global__ void attn_o_kernel(float* __restrict__ out) {
    const int b    = blockIdx.y;
    const int wl   = threadIdx.x >> 5;
    const int lane = threadIdx.x & 31;
    const int h    = blockIdx.x * 8 + wl;

    const size_t base = (size_t)b * F_OUT + (size_t)h * 32;
    const float qv = g_q[base + lane] * ATTN_SCALE;
    const float kv = g_k[base + lane];
    const float vv = g_v[base + lane];
    const float* __restrict__ rz = g_rzt + (size_t)b * 1024 + lane;

    float accv = 0.0f;
    #pragma unroll
    for (int j = 0; j < 32; j++) {
        float kj = __shfl_sync(0xffffffffu, kv, j);
        float vj = __shfl_sync(0xffffffffu, vv, j);
        accv += __expf(qv * kj) * vj * rz[j * 32];
    }
    out[((size_t)b * HEADS + h) * 32 + lane] = accv;
}

// ---------------------------------------------------------------------------
extern "C" void kernel_launch(void* const* d_in, const int* in_sizes, int n_in,
                              void* d_out, int out_size) {
    const float* x  = (const float*)d_in[0];
    const float* Wq = (const float*)d_in[1];
    const float* bq = (const float*)d_in[2];
    const float* Wk = (const float*)d_in[3];
    const float* bk = (const float*)d_in[4];
    const float* Wv = (const float*)d_in[5];
    const float* bv = (const float*)d_in[6];
    // d_in[7] (tw): constant along softmax axis (heads) -> cancels; unused.
    (void)in_sizes; (void)n_in; (void)out_size;

    round_x_kernel<<<64, 256>>>(x);
    qkv_gemm_kernel<<<dim3(128, 3), 256>>>(Wq, bq, Wk, bk, Wv, bv);
    attn_z_kernel<<<dim3(32, 4), 256>>>();
    attn_o_kernel<<<dim3(64, 32), 256>>>((float*)d_out);
}

// round 2
// speedup vs baseline: 1.7255x; 1.7255x over previous
#include <cuda_runtime.h>
#include <cstdint>

#define F_IN   8192
#define F_OUT  16384
#define BATCH  32
#define HEADS  512

// Scratch (static __device__ — allocation-free per harness rules)
__device__ float g_xr[BATCH * F_IN];    // tf32-rounded x
__device__ float g_q[BATCH * F_OUT];
__device__ float g_k[BATCH * F_OUT];
__device__ float g_v[BATCH * F_OUT];
__device__ float g_rzt[BATCH * 32 * 32]; // 1/Z transposed: [b][j][i]

__device__ __forceinline__ uint32_t tf32_rna(float f) {
    uint32_t u;
    asm("cvt.rna.tf32.f32 %0, %1;" : "=r"(u) : "f"(f));
    return u;
}

__device__ __forceinline__ float gelu_exact(float v) {
    return 0.5f * v * (1.0f + erff(v * 0.70710678118654752f));
}

// ---------------------------------------------------------------------------
// Kernel 0: pre-round x to tf32 (RNA) once.
// ---------------------------------------------------------------------------
__global__ void round_x_kernel(const float* __restrict__ x) {
    int i = blockIdx.x * blockDim.x + threadIdx.x;
    int stride = gridDim.x * blockDim.x;
    for (; i < BATCH * F_IN; i += stride)
        g_xr[i] = __uint_as_float(tf32_rna(x[i]));
}

// ---------------------------------------------------------------------------
// Kernel 1: QKV GEMM, computed TRANSPOSED: D^T[m][b] = sum_k W[m][k]*x[b][k]
//   A (M-side)   = W   : streamed, coalesced cp.async -> SMEM (read once)
//   B (N-side)   = x^T : tiny, staged per chunk, reused by all warps
// CTA: 256 thr / 8 warps. M-tile 256 (warp m32), N=32, K-chunk 32, 2 stages.
// k-permutation inside each k8: logical tq -> phys 2tq, tq+4 -> 2tq+1,
// applied to BOTH operands => all fragment loads are aligned LDS.64,
// conflict-free with row stride 40 floats (banks 8g+2tq all distinct).
// ---------------------------------------------------------------------------
#define MMA_TF32(d, a0,a1,a2,a3, b0,b1)                                     \
    asm volatile("mma.sync.aligned.m16n8k8.row.col.f32.tf32.tf32.f32 "      \
        "{%0,%1,%2,%3}, {%4,%5,%6,%7}, {%8,%9}, {%0,%1,%2,%3};"             \
        : "+f"(d[0]), "+f"(d[1]), "+f"(d[2]), "+f"(d[3])                    \
        : "r"(a0), "r"(a1), "r"(a2), "r"(a3), "r"(b0), "r"(b1))

#define KC        32            // K-chunk
#define RS        40            // row stride in floats (32 + 8 pad)
#define MT        256           // CTA M-tile (rows of W)
#define WSF       (MT * RS)     // 10240 floats per W stage
#define XSF       (BATCH * RS)  // 1280 floats per x stage
#define STAGEF    (WSF + XSF)   // 11520 floats per stage
#define SMEM_BYTES (2 * STAGEF * 4)   // 92160 B

__device__ __forceinline__ void cp16(float* dst, const float* src) {
    uint32_t d = (uint32_t)__cvta_generic_to_shared(dst);
    asm volatile("cp.async.cg.shared.global [%0], [%1], 16;" :: "r"(d), "l"(src));
}

__global__ __launch_bounds__(256, 2)
void qkv_gemm_kernel(const float* __restrict__ Wq, const float* __restrict__ bq,
                     const float* __restrict__ Wk, const float* __restrict__ bk,
                     const float* __restrict__ Wv, const float* __restrict__ bv) {
    extern __shared__ float smem[];

    const float* W; const float* bias; float* out;
    if (blockIdx.y == 0)      { W = Wq; bias = bq; out = g_q; }
    else if (blockIdx.y == 1) { W = Wk; bias = bk; out = g_k; }
    else                      { W = Wv; bias = bv; out = g_v; }

    const int tid  = threadIdx.x;
    const int warp = tid >> 5;
    const int lane = tid & 31;
    const int g    = lane >> 2;       // groupID (0..7)
    const int tq   = lane & 3;        // thread-in-group (0..3)
    const int mb   = blockIdx.x * MT; // CTA's first W row

    float acc[2][4][4];               // [m16-subtile][n-tile(batch/8)][frag]
    #pragma unroll
    for (int a = 0; a < 2; a++)
        #pragma unroll
        for (int b = 0; b < 4; b++)
            #pragma unroll
            for (int r = 0; r < 4; r++) acc[a][b][r] = 0.0f;

    // stage one K-chunk: W tile 256x32 + x tile 32x32, both coalesced
    auto stage = [&](int buf, int kc) {
        float* ws = smem + buf * STAGEF;
        float* xs = ws + WSF;
        #pragma unroll
        for (int r = 0; r < 8; r++) {
            int idx = tid + r * 256;            // 2048 float4
            int row = idx >> 3;
            int c4  = idx & 7;
            cp16(&ws[row * RS + c4 * 4],
                 W + (size_t)(mb + row) * F_IN + kc + c4 * 4);
        }
        {
            int b  = tid >> 3;
            int c4 = tid & 7;
            cp16(&xs[b * RS + c4 * 4],
                 g_xr + (size_t)b * F_IN + kc + c4 * 4);
        }
        asm volatile("cp.async.commit_group;");
    };

    stage(0, 0);

    const int NCHUNK = F_IN / KC;     // 256
    for (int c = 0; c < NCHUNK; c++) {
        asm volatile("cp.async.wait_group 0;");
        __syncthreads();
        if (c + 1 < NCHUNK) stage((c + 1) & 1, (c + 1) * KC);

        const float* ws = smem + (c & 1) * STAGEF;
        const float* xs = ws + WSF;

        #pragma unroll
        for (int s = 0; s < 4; s++) {
            const int kp = 8 * s + 2 * tq;    // physical k offset in chunk

            // A (W) fragments: two m16 subtiles, rows warp*32 + {g,g+8,g+16,g+24}
            uint32_t A[2][4];
            #pragma unroll
            for (int mt = 0; mt < 2; mt++) {
                const int r0 = warp * 32 + mt * 16 + g;
                float2 lo = *reinterpret_cast<const float2*>(&ws[r0 * RS + kp]);
                float2 hi = *reinterpret_cast<const float2*>(&ws[(r0 + 8) * RS + kp]);
                A[mt][0] = tf32_rna(lo.x);   // a0: (m=g,   k'=tq)
                A[mt][1] = tf32_rna(hi.x);   // a1: (m=g+8, k'=tq)
                A[mt][2] = tf32_rna(lo.y);   // a2: (m=g,   k'=tq+4)
                A[mt][3] = tf32_rna(hi.y);   // a3: (m=g+8, k'=tq+4)
            }

            // B (x^T) fragments: n = batch, 4 n-tiles of 8 (already tf32)
            float2 bvf[4];
            #pragma unroll
            for (int j = 0; j < 4; j++)
                bvf[j] = *reinterpret_cast<const float2*>(&xs[(j * 8 + g) * RS + kp]);

            #pragma unroll
            for (int mt = 0; mt < 2; mt++)
                #pragma unroll
                for (int j = 0; j < 4; j++)
                    MMA_TF32(acc[mt][j], A[mt][0], A[mt][1], A[mt][2], A[mt][3],
                             __float_as_uint(bvf[j].x), __float_as_uint(bvf[j].y));
        }
    }

    // Epilogue: bias + exact GELU, store transposed into [batch][F_OUT]
    #pragma unroll
    for (int mt = 0; mt < 2; mt++) {
        const int r0 = mb + warp * 32 + mt * 16 + g;   // output feature index
        const float bia0 = bias[r0];
        const float bia1 = bias[r0 + 8];
        #pragma unroll
        for (int j = 0; j < 4; j++) {
            const int bt = j * 8 + 2 * tq;             // batch index
            out[(size_t)bt       * F_OUT + r0    ] = gelu_exact(acc[mt][j][0] + bia0);
            out[(size_t)(bt + 1) * F_OUT + r0    ] = gelu_exact(acc[mt][j][1] + bia0);
            out[(size_t)bt       * F_OUT + r0 + 8] = gelu_exact(acc[mt][j][2] + bia1);
            out[(size_t)(bt + 1) * F_OUT + r0 + 8] = gelu_exact(acc[mt][j][3] + bia1);
        }
    }
}

// ---------------------------------------------------------------------------
// Kernel 2: softmax denominators over the HEADS axis (bias cancels).
// rZt[b][j][i] = 1 / sum_h exp(c * q[b,h,i] * k[b,h,j])
// ---------------------------------------------------------------------------
#define ATTN_SCALE 0.17677669529663687f   // 1/sqrt(32)

__global__ void attn_z_kernel() {
    const int b  = blockIdx.x;
    const int iq = blockIdx.y;
    const int tid = threadIdx.x;
    const int il  = tid >> 5;
    const int j   = tid & 31;
    const int i   = iq * 8 + il;

    __shared__ float qs[32][8];
    __shared__ float ks[32][32];

    const float* __restrict__ qb = g_q + (size_t)b * F_OUT;
    const float* __restrict__ kb = g_k + (size_t)b * F_OUT;

    float z = 0.0f;
    for (int hc = 0; hc < 16; hc++) {
        {
            int hh = tid >> 3, ii = tid & 7;
            qs[hh][ii] = qb[(size_t)(hc * 32 + hh) * 32 + iq * 8 + ii];
            #pragma unroll
            for (int r = 0; r < 4; r++) {
                int idx = tid + r * 256;
                int hh2 = idx >> 5, jj = idx & 31;
                ks[hh2][jj] = kb[(size_t)(hc * 32 + hh2) * 32 + jj];
            }
        }
        __syncthreads();
        #pragma unroll
        for (int hh = 0; hh < 32; hh++)
            z += __expf(ATTN_SCALE * qs[hh][il] * ks[hh][j]);
        __syncthreads();
    }
    g_rzt[(size_t)b * 1024 + j * 32 + i] = 1.0f / z;
}

// ---------------------------------------------------------------------------
// Kernel 3: out[b,h,i] = sum_j exp(c*q_i*k_j) * rZ[b,i,j] * v[b,h,j]
// ---------------------------------------------------------------------------
__global__ void attn_o_kernel(float* __restrict__ out) {
    const int b    = blockIdx.y;
    const int wl   = threadIdx.x >> 5;
    const int lane = threadIdx.x & 31;
    const int h    = blockIdx.x * 8 + wl;

    const size_t base = (size_t)b * F_OUT + (size_t)h * 32;
    const float qv = g_q[base + lane] * ATTN_SCALE;
    const float kv = g_k[base + lane];
    const float vv = g_v[base + lane];
    const float* __restrict__ rz = g_rzt + (size_t)b * 1024 + lane;

    float accv = 0.0f;
    #pragma unroll
    for (int j = 0; j < 32; j++) {
        float kj = __shfl_sync(0xffffffffu, kv, j);
        float vj = __shfl_sync(0xffffffffu, vv, j);
        accv += __expf(qv * kj) * vj * rz[j * 32];
    }
    out[((size_t)b * HEADS + h) * 32 + lane] = accv;
}

// ---------------------------------------------------------------------------
extern "C" void kernel_launch(void* const* d_in, const int* in_sizes, int n_in,
                              void* d_out, int out_size) {
    const float* x  = (const float*)d_in[0];
    const float* Wq = (const float*)d_in[1];
    const float* bq = (const float*)d_in[2];
    const float* Wk = (const float*)d_in[3];
    const float* bk = (const float*)d_in[4];
    const float* Wv = (const float*)d_in[5];
    const float* bv = (const float*)d_in[6];
    // d_in[7] (tw): constant along softmax axis (heads) -> cancels; unused.
    (void)in_sizes; (void)n_in; (void)out_size;

    cudaFuncSetAttribute(qkv_gemm_kernel,
                         cudaFuncAttributeMaxDynamicSharedMemorySize, SMEM_BYTES);

    round_x_kernel<<<64, 256>>>(x);
    qkv_gemm_kernel<<<dim3(F_OUT / MT, 3), 256, SMEM_BYTES>>>(Wq, bq, Wk, bk, Wv, bv);
    attn_z_kernel<<<dim3(32, 4), 256>>>();
    attn_o_kernel<<<dim3(64, 32), 256>>>((float*)d_out);
}

// round 4
// speedup vs baseline: 2.2109x; 1.2813x over previous
#include <cuda_runtime.h>
#include <cstdint>

#define F_IN   8192
#define F_OUT  16384
#define BATCH  32
#define HEADS  512

// Scratch (static __device__ — allocation-free per harness rules)
__device__ float g_xr[BATCH * F_IN];    // tf32(RNA)-rounded x
__device__ float g_q[BATCH * F_OUT];
__device__ float g_k[BATCH * F_OUT];
__device__ float g_v[BATCH * F_OUT];
__device__ float g_rzt[BATCH * 32 * 32]; // 1/Z transposed: [b][j][i]

__device__ __forceinline__ uint32_t tf32_rna(float f) {
    uint32_t u;
    asm("cvt.rna.tf32.f32 %0, %1;" : "=r"(u) : "f"(f));
    return u;
}

__device__ __forceinline__ float gelu_exact(float v) {
    return 0.5f * v * (1.0f + erff(v * 0.70710678118654752f));
}

// ---------------------------------------------------------------------------
// Kernel 0: pre-round x to tf32 (RNA) once.
// ---------------------------------------------------------------------------
__global__ void round_x_kernel(const float* __restrict__ x) {
    int i = blockIdx.x * blockDim.x + threadIdx.x;
    int stride = gridDim.x * blockDim.x;
    for (; i < BATCH * F_IN; i += stride)
        g_xr[i] = __uint_as_float(tf32_rna(x[i]));
}

// ---------------------------------------------------------------------------
// Kernel 1: QKV GEMM, transposed: D^T[m][b] = sum_k W[m][k]*x[b][k]
//   A (M-side) = W  : streamed, coalesced cp.async -> SMEM (read once)
//   B (N-side) = x^T: tiny, staged per chunk, reused by all warps
// CTA: 128 thr / 4 warps, M-tile 128 (warp m32), N=32, K-chunk 32, 3 stages.
// Grid 384 CTAs @ occ 3 -> all resident in ONE wave (no imbalance tail).
// k-permutation inside each k8 (logical tq -> phys 2tq, tq+4 -> 2tq+1) applied
// to BOTH operands => all fragment loads are aligned LDS.64, conflict-free
// with row stride 40 floats.
// ---------------------------------------------------------------------------
#define MMA_TF32(d, a0,a1,a2,a3, b0,b1)                                     \
    asm volatile("mma.sync.aligned.m16n8k8.row.col.f32.tf32.tf32.f32 "      \
        "{%0,%1,%2,%3}, {%4,%5,%6,%7}, {%8,%9}, {%0,%1,%2,%3};"             \
        : "+f"(d[0]), "+f"(d[1]), "+f"(d[2]), "+f"(d[3])                    \
        : "r"(a0), "r"(a1), "r"(a2), "r"(a3), "r"(b0), "r"(b1))

#define KC        32            // K-chunk
#define RS        40            // row stride in floats (32 + 8 pad)
#define MT        128           // CTA M-tile (rows of W)
#define NSTAGE    3
#define WSF       (MT * RS)     // 5120 floats per W stage
#define XSF       (BATCH * RS)  // 1280 floats per x stage
#define STAGEF    (WSF + XSF)   // 6400 floats per stage
#define SMEM_BYTES (NSTAGE * STAGEF * 4)   // 76800 B

__device__ __forceinline__ void cp16(float* dst, const float* src) {
    uint32_t d = (uint32_t)__cvta_generic_to_shared(dst);
    asm volatile("cp.async.cg.shared.global [%0], [%1], 16;" :: "r"(d), "l"(src));
}

__global__ __launch_bounds__(128, 3)
void qkv_gemm_kernel(const float* __restrict__ Wq, const float* __restrict__ bq,
                     const float* __restrict__ Wk, const float* __restrict__ bk,
                     const float* __restrict__ Wv, const float* __restrict__ bv) {
    extern __shared__ float smem[];

    const float* W; const float* bias; float* out;
    if (blockIdx.y == 0)      { W = Wq; bias = bq; out = g_q; }
    else if (blockIdx.y == 1) { W = Wk; bias = bk; out = g_k; }
    else                      { W = Wv; bias = bv; out = g_v; }

    const int tid  = threadIdx.x;
    const int warp = tid >> 5;
    const int lane = tid & 31;
    const int g    = lane >> 2;       // groupID (0..7)
    const int tq   = lane & 3;        // thread-in-group (0..3)
    const int mb   = blockIdx.x * MT; // CTA's first W row

    float acc[2][4][4];               // [m16-subtile][n-tile(batch/8)][frag]
    #pragma unroll
    for (int a = 0; a < 2; a++)
        #pragma unroll
        for (int b = 0; b < 4; b++)
            #pragma unroll
            for (int r = 0; r < 4; r++) acc[a][b][r] = 0.0f;

    // stage one K-chunk: W tile 128x32 + x tile 32x32, both coalesced
    auto stage = [&](int s, int c) {
        float* ws = smem + s * STAGEF;
        float* xs = ws + WSF;
        const int kc = c * KC;
        #pragma unroll
        for (int r = 0; r < 8; r++) {
            int idx = tid + r * 128;            // 1024 float4
            int row = idx >> 3;
            int c4  = idx & 7;
            cp16(&ws[row * RS + c4 * 4],
                 W + (size_t)(mb + row) * F_IN + kc + c4 * 4);
        }
        #pragma unroll
        for (int r = 0; r < 2; r++) {
            int idx = tid + r * 128;            // 256 float4
            int b   = idx >> 3;
            int c4  = idx & 7;
            cp16(&xs[b * RS + c4 * 4],
                 g_xr + (size_t)b * F_IN + kc + c4 * 4);
        }
        asm volatile("cp.async.commit_group;");
    };

    stage(0, 0); stage(1, 1); stage(2, 2);

    const int NCHUNK = F_IN / KC;     // 256
    for (int c = 0; c < NCHUNK; c++) {
        const int rem = NCHUNK - 1 - c;
        if (rem >= 2)      asm volatile("cp.async.wait_group 2;");
        else if (rem == 1) asm volatile("cp.async.wait_group 1;");
        else               asm volatile("cp.async.wait_group 0;");
        __syncthreads();

        const float* ws = smem + (c % NSTAGE) * STAGEF;
        const float* xs = ws + WSF;

        #pragma unroll
        for (int s = 0; s < 4; s++) {
            const int kp = 8 * s + 2 * tq;    // physical k offset in chunk

            // A (W) fragments: two m16 subtiles, rows warp*32 + {g,g+8,g+16,g+24}
            uint32_t A[2][4];
            #pragma unroll
            for (int mt = 0; mt < 2; mt++) {
                const int r0 = warp * 32 + mt * 16 + g;
                float2 lo = *reinterpret_cast<const float2*>(&ws[r0 * RS + kp]);
                float2 hi = *reinterpret_cast<const float2*>(&ws[(r0 + 8) * RS + kp]);
                A[mt][0] = tf32_rna(lo.x);   // a0: (m=g,   k'=tq)
                A[mt][1] = tf32_rna(hi.x);   // a1: (m=g+8, k'=tq)
                A[mt][2] = tf32_rna(lo.y);   // a2: (m=g,   k'=tq+4)
                A[mt][3] = tf32_rna(hi.y);   // a3: (m=g+8, k'=tq+4)
            }

            // B (x^T) fragments: n = batch, 4 n-tiles of 8 (already tf32)
            float2 bvf[4];
            #pragma unroll
            for (int j = 0; j < 4; j++)
                bvf[j] = *reinterpret_cast<const float2*>(&xs[(j * 8 + g) * RS + kp]);

            #pragma unroll
            for (int mt = 0; mt < 2; mt++)
                #pragma unroll
                for (int j = 0; j < 4; j++)
                    MMA_TF32(acc[mt][j], A[mt][0], A[mt][1], A[mt][2], A[mt][3],
                             __float_as_uint(bvf[j].x), __float_as_uint(bvf[j].y));
        }

        __syncthreads();                      // all reads of buf done
        if (c + NSTAGE < NCHUNK) stage(c % NSTAGE, c + NSTAGE);
    }

    // Epilogue: bias + exact GELU, store transposed into [batch][F_OUT]
    #pragma unroll
    for (int mt = 0; mt < 2; mt++) {
        const int r0 = mb + warp * 32 + mt * 16 + g;   // output feature index
        const float bia0 = bias[r0];
        const float bia1 = bias[r0 + 8];
        #pragma unroll
        for (int j = 0; j < 4; j++) {
            const int bt = j * 8 + 2 * tq;             // batch index
            out[(size_t)bt       * F_OUT + r0    ] = gelu_exact(acc[mt][j][0] + bia0);
            out[(size_t)(bt + 1) * F_OUT + r0    ] = gelu_exact(acc[mt][j][1] + bia0);
            out[(size_t)bt       * F_OUT + r0 + 8] = gelu_exact(acc[mt][j][2] + bia1);
            out[(size_t)(bt + 1) * F_OUT + r0 + 8] = gelu_exact(acc[mt][j][3] + bia1);
        }
    }
}

// ---------------------------------------------------------------------------
// Kernel 2: softmax denominators over the HEADS axis (bias cancels).
// rZt[b][j][i] = 1 / sum_h exp(c * q[b,h,i] * k[b,h,j])
// ---------------------------------------------------------------------------
#define ATTN_SCALE 0.17677669529663687f   // 1/sqrt(32)

__global__ void attn_z_kernel() {
    const int b  = blockIdx.x;
    const int iq = blockIdx.y;
    const int tid = threadIdx.x;
    const int il  = tid >> 5;
    const int j   = tid & 31;
    const int i   = iq * 8 + il;

    __shared__ float qs[32][8];
    __shared__ float ks[32][32];

    const float* __restrict__ qb = g_q + (size_t)b * F_OUT;
    const float* __restrict__ kb = g_k + (size_t)b * F_OUT;

    float z = 0.0f;
    for (int hc = 0; hc < 16; hc++) {
        {
            int hh = tid >> 3, ii = tid & 7;
            qs[hh][ii] = qb[(size_t)(hc * 32 + hh) * 32 + iq * 8 + ii];
            #pragma unroll
            for (int r = 0; r < 4; r++) {
                int idx = tid + r * 256;
                int hh2 = idx >> 5, jj = idx & 31;
                ks[hh2][jj] = kb[(size_t)(hc * 32 + hh2) * 32 + jj];
            }
        }
        __syncthreads();
        #pragma unroll
        for (int hh = 0; hh < 32; hh++)
            z += __expf(ATTN_SCALE * qs[hh][il] * ks[hh][j]);
        __syncthreads();
    }
    g_rzt[(size_t)b * 1024 + j * 32 + i] = 1.0f / z;
}

// ---------------------------------------------------------------------------
// Kernel 3: out[b,h,i] = sum_j exp(c*q_i*k_j) * rZ[b,i,j] * v[b,h,j]
// ---------------------------------------------------------------------------
__global__ void attn_o_kernel(float* __restrict__ out) {
    const int b    = blockIdx.y;
    const int wl   = threadIdx.x >> 5;
    const int lane = threadIdx.x & 31;
    const int h    = blockIdx.x * 8 + wl;

    const size_t base = (size_t)b * F_OUT + (size_t)h * 32;
    const float qv = g_q[base + lane] * ATTN_SCALE;
    const float kv = g_k[base + lane];
    const float vv = g_v[base + lane];
    const float* __restrict__ rz = g_rzt + (size_t)b * 1024 + lane;

    float accv = 0.0f;
    #pragma unroll
    for (int j = 0; j < 32; j++) {
        float kj = __shfl_sync(0xffffffffu, kv, j);
        float vj = __shfl_sync(0xffffffffu, vv, j);
        accv += __expf(qv * kj) * vj * rz[j * 32];
    }
    out[((size_t)b * HEADS + h) * 32 + lane] = accv;
}

// ---------------------------------------------------------------------------
extern "C" void kernel_launch(void* const* d_in, const int* in_sizes, int n_in,
                              void* d_out, int out_size) {
    const float* x  = (const float*)d_in[0];
    const float* Wq = (const float*)d_in[1];
    const float* bq = (const float*)d_in[2];
    const float* Wk = (const float*)d_in[3];
    const float* bk = (const float*)d_in[4];
    const float* Wv = (const float*)d_in[5];
    const float* bv = (const float*)d_in[6];
    // d_in[7] (tw): constant along softmax axis (heads) -> cancels; unused.
    (void)in_sizes; (void)n_in; (void)out_size;

    cudaFuncSetAttribute(qkv_gemm_kernel,
                         cudaFuncAttributeMaxDynamicSharedMemorySize, SMEM_BYTES);

    round_x_kernel<<<64, 256>>>(x);
    qkv_gemm_kernel<<<dim3(F_OUT / MT, 3), 128, SMEM_BYTES>>>(Wq, bq, Wk, bk, Wv, bv);
    attn_z_kernel<<<dim3(32, 4), 256>>>();
    attn_o_kernel<<<dim3(64, 32), 256>>>((float*)d_out);
}

// round 5
// speedup vs baseline: 2.2617x; 1.0230x over previous
#include <cuda_runtime.h>
#include <cstdint>

#define F_IN   8192
#define F_OUT  16384
#define BATCH  32
#define HEADS  512

// Scratch (static __device__ — allocation-free per harness rules)
__device__ float g_xr[BATCH * F_IN];    // tf32(RNA)-rounded x
__device__ float g_q[BATCH * F_OUT];
__device__ float g_k[BATCH * F_OUT];
__device__ float g_v[BATCH * F_OUT];
__device__ float g_rzt[BATCH * 32 * 32]; // 1/Z transposed: [b][j][i]

__device__ __forceinline__ uint32_t tf32_rna(float f) {
    uint32_t u;
    asm("cvt.rna.tf32.f32 %0, %1;" : "=r"(u) : "f"(f));
    return u;
}

__device__ __forceinline__ float gelu_exact(float v) {
    return 0.5f * v * (1.0f + erff(v * 0.70710678118654752f));
}

// ---------------------------------------------------------------------------
// Kernel 0: pre-round x to tf32 (RNA) once. Vectorized float4.
// 65536 float4 over 256 blocks x 256 threads = 1 element each.
// ---------------------------------------------------------------------------
__global__ void round_x_kernel(const float4* __restrict__ x) {
    int i = blockIdx.x * blockDim.x + threadIdx.x;
    float4 v = x[i];
    float4 o;
    o.x = __uint_as_float(tf32_rna(v.x));
    o.y = __uint_as_float(tf32_rna(v.y));
    o.z = __uint_as_float(tf32_rna(v.z));
    o.w = __uint_as_float(tf32_rna(v.w));
    reinterpret_cast<float4*>(g_xr)[i] = o;
}

// ---------------------------------------------------------------------------
// Kernel 1: QKV GEMM, transposed: D^T[m][b] = sum_k W[m][k]*x[b][k]
//   A (M-side) = W  : streamed, coalesced cp.async -> SMEM (read once)
//   B (N-side) = x^T: tiny, staged per chunk, reused by all warps
// CTA: 128 thr / 4 warps, M-tile 128 (warp m32), N=32, K-chunk 32, 3 stages.
// Grid 384 CTAs @ occ 3 -> all resident in ONE wave.
// k-permutation inside each k8 (logical tq -> phys 2tq, tq+4 -> 2tq+1) applied
// to BOTH operands => all fragment loads are aligned LDS.64, conflict-free
// with row stride 40 floats.
// ---------------------------------------------------------------------------
#define MMA_TF32(d, a0,a1,a2,a3, b0,b1)                                     \
    asm volatile("mma.sync.aligned.m16n8k8.row.col.f32.tf32.tf32.f32 "      \
        "{%0,%1,%2,%3}, {%4,%5,%6,%7}, {%8,%9}, {%0,%1,%2,%3};"             \
        : "+f"(d[0]), "+f"(d[1]), "+f"(d[2]), "+f"(d[3])                    \
        : "r"(a0), "r"(a1), "r"(a2), "r"(a3), "r"(b0), "r"(b1))

#define KC        32            // K-chunk
#define RS        40            // row stride in floats (32 + 8 pad)
#define MT        128           // CTA M-tile (rows of W)
#define NSTAGE    3
#define WSF       (MT * RS)     // 5120 floats per W stage
#define XSF       (BATCH * RS)  // 1280 floats per x stage
#define STAGEF    (WSF + XSF)   // 6400 floats per stage
#define SMEM_BYTES (NSTAGE * STAGEF * 4)   // 76800 B

__device__ __forceinline__ void cp16(float* dst, const float* src) {
    uint32_t d = (uint32_t)__cvta_generic_to_shared(dst);
    asm volatile("cp.async.cg.shared.global [%0], [%1], 16;" :: "r"(d), "l"(src));
}

__global__ __launch_bounds__(128, 3)
void qkv_gemm_kernel(const float* __restrict__ Wq, const float* __restrict__ bq,
                     const float* __restrict__ Wk, const float* __restrict__ bk,
                     const float* __restrict__ Wv, const float* __restrict__ bv) {
    extern __shared__ float smem[];

    const float* W; const float* bias; float* out;
    if (blockIdx.y == 0)      { W = Wq; bias = bq; out = g_q; }
    else if (blockIdx.y == 1) { W = Wk; bias = bk; out = g_k; }
    else                      { W = Wv; bias = bv; out = g_v; }

    const int tid  = threadIdx.x;
    const int warp = tid >> 5;
    const int lane = tid & 31;
    const int g    = lane >> 2;       // groupID (0..7)
    const int tq   = lane & 3;        // thread-in-group (0..3)
    const int mb   = blockIdx.x * MT; // CTA's first W row

    float acc[2][4][4];               // [m16-subtile][n-tile(batch/8)][frag]
    #pragma unroll
    for (int a = 0; a < 2; a++)
        #pragma unroll
        for (int b = 0; b < 4; b++)
            #pragma unroll
            for (int r = 0; r < 4; r++) acc[a][b][r] = 0.0f;

    // stage one K-chunk: W tile 128x32 + x tile 32x32, both coalesced
    auto stage = [&](int s, int c) {
        float* ws = smem + s * STAGEF;
        float* xs = ws + WSF;
        const int kc = c * KC;
        #pragma unroll
        for (int r = 0; r < 8; r++) {
            int idx = tid + r * 128;            // 1024 float4
            int row = idx >> 3;
            int c4  = idx & 7;
            cp16(&ws[row * RS + c4 * 4],
                 W + (size_t)(mb + row) * F_IN + kc + c4 * 4);
        }
        #pragma unroll
        for (int r = 0; r < 2; r++) {
            int idx = tid + r * 128;            // 256 float4
            int b   = idx >> 3;
            int c4  = idx & 7;
            cp16(&xs[b * RS + c4 * 4],
                 g_xr + (size_t)b * F_IN + kc + c4 * 4);
        }
        asm volatile("cp.async.commit_group;");
    };

    stage(0, 0); stage(1, 1); stage(2, 2);

    const int NCHUNK = F_IN / KC;     // 256
    for (int c = 0; c < NCHUNK; c++) {
        const int rem = NCHUNK - 1 - c;
        if (rem >= 2)      asm volatile("cp.async.wait_group 2;");
        else if (rem == 1) asm volatile("cp.async.wait_group 1;");
        else               asm volatile("cp.async.wait_group 0;");
        __syncthreads();

        const float* ws = smem + (c % NSTAGE) * STAGEF;
        const float* xs = ws + WSF;

        #pragma unroll
        for (int s = 0; s < 4; s++) {
            const int kp = 8 * s + 2 * tq;    // physical k offset in chunk

            // A (W) fragments: two m16 subtiles, rows warp*32 + {g,g+8,g+16,g+24}
            uint32_t A[2][4];
            #pragma unroll
            for (int mt = 0; mt < 2; mt++) {
                const int r0 = warp * 32 + mt * 16 + g;
                float2 lo = *reinterpret_cast<const float2*>(&ws[r0 * RS + kp]);
                float2 hi = *reinterpret_cast<const float2*>(&ws[(r0 + 8) * RS + kp]);
                A[mt][0] = tf32_rna(lo.x);   // a0: (m=g,   k'=tq)
                A[mt][1] = tf32_rna(hi.x);   // a1: (m=g+8, k'=tq)
                A[mt][2] = tf32_rna(lo.y);   // a2: (m=g,   k'=tq+4)
                A[mt][3] = tf32_rna(hi.y);   // a3: (m=g+8, k'=tq+4)
            }

            // B (x^T) fragments: n = batch, 4 n-tiles of 8 (already tf32)
            float2 bvf[4];
            #pragma unroll
            for (int j = 0; j < 4; j++)
                bvf[j] = *reinterpret_cast<const float2*>(&xs[(j * 8 + g) * RS + kp]);

            #pragma unroll
            for (int mt = 0; mt < 2; mt++)
                #pragma unroll
                for (int j = 0; j < 4; j++)
                    MMA_TF32(acc[mt][j], A[mt][0], A[mt][1], A[mt][2], A[mt][3],
                             __float_as_uint(bvf[j].x), __float_as_uint(bvf[j].y));
        }

        __syncthreads();                      // all reads of buf done
        if (c + NSTAGE < NCHUNK) stage(c % NSTAGE, c + NSTAGE);
    }

    // Epilogue: bias + exact GELU, store transposed into [batch][F_OUT]
    #pragma unroll
    for (int mt = 0; mt < 2; mt++) {
        const int r0 = mb + warp * 32 + mt * 16 + g;   // output feature index
        const float bia0 = bias[r0];
        const float bia1 = bias[r0 + 8];
        #pragma unroll
        for (int j = 0; j < 4; j++) {
            const int bt = j * 8 + 2 * tq;             // batch index
            out[(size_t)bt       * F_OUT + r0    ] = gelu_exact(acc[mt][j][0] + bia0);
            out[(size_t)(bt + 1) * F_OUT + r0    ] = gelu_exact(acc[mt][j][1] + bia0);
            out[(size_t)bt       * F_OUT + r0 + 8] = gelu_exact(acc[mt][j][2] + bia1);
            out[(size_t)(bt + 1) * F_OUT + r0 + 8] = gelu_exact(acc[mt][j][3] + bia1);
        }
    }
}

// ---------------------------------------------------------------------------
// Kernel 2: softmax denominators over the HEADS axis (bias cancels).
// rZt[b][j][i] = 1 / sum_h exp(c * q[b,h,i] * k[b,h,j])
// ---------------------------------------------------------------------------
#define ATTN_SCALE 0.17677669529663687f   // 1/sqrt(32)

__global__ void attn_z_kernel() {
    const int b  = blockIdx.x;
    const int iq = blockIdx.y;
    const int tid = threadIdx.x;
    const int il  = tid >> 5;
    const int j   = tid & 31;
    const int i   = iq * 8 + il;

    __shared__ float qs[32][8];
    __shared__ float ks[32][32];

    const float* __restrict__ qb = g_q + (size_t)b * F_OUT;
    const float* __restrict__ kb = g_k + (size_t)b * F_OUT;

    float z = 0.0f;
    for (int hc = 0; hc < 16; hc++) {
        {
            int hh = tid >> 3, ii = tid & 7;
            qs[hh][ii] = qb[(size_t)(hc * 32 + hh) * 32 + iq * 8 + ii];
            #pragma unroll
            for (int r = 0; r < 4; r++) {
                int idx = tid + r * 256;
                int hh2 = idx >> 5, jj = idx & 31;
                ks[hh2][jj] = kb[(size_t)(hc * 32 + hh2) * 32 + jj];
            }
        }
        __syncthreads();
        #pragma unroll
        for (int hh = 0; hh < 32; hh++)
            z += __expf(ATTN_SCALE * qs[hh][il] * ks[hh][j]);
        __syncthreads();
    }
    g_rzt[(size_t)b * 1024 + j * 32 + i] = 1.0f / z;
}

// ---------------------------------------------------------------------------
// Kernel 3: out[b,h,i] = sum_j exp(c*q_i*k_j) * rZ[b,i,j] * v[b,h,j]
// Grid (64, 32), block 256. Warp wl -> head h = bx*8+wl, lanes = i.
// (k,v) staged in SMEM as float2 (LDS.64 broadcast per j, replaces 2 shfls),
// rz tile (4KB per b) staged in SMEM (LDS.32 replaces per-iter LDG).
// ---------------------------------------------------------------------------
__global__ void attn_o_kernel(float* __restrict__ out) {
    __shared__ float2 kvs[8][32];
    __shared__ float  rzs[1024];

    const int b    = blockIdx.y;
    const int tid  = threadIdx.x;
    const int wl   = tid >> 5;
    const int lane = tid & 31;
    const int h    = blockIdx.x * 8 + wl;

    const size_t base = (size_t)b * F_OUT + (size_t)h * 32;

    // stage: each warp loads its own head's k,v (coalesced), plus rz tile
    {
        float kk = g_k[base + lane];
        float vv = g_v[base + lane];
        kvs[wl][lane] = make_float2(kk, vv);
        #pragma unroll
        for (int r = 0; r < 4; r++)
            rzs[tid + r * 256] = g_rzt[(size_t)b * 1024 + tid + r * 256];
    }
    const float qv = g_q[base + lane] * ATTN_SCALE;
    __syncthreads();

    float accv = 0.0f;
    #pragma unroll
    for (int j = 0; j < 32; j++) {
        float2 kv = kvs[wl][j];                 // LDS.64 broadcast
        accv += __expf(qv * kv.x) * kv.y * rzs[j * 32 + lane];
    }
    out[((size_t)b * HEADS + h) * 32 + lane] = accv;
}

// ---------------------------------------------------------------------------
extern "C" void kernel_launch(void* const* d_in, const int* in_sizes, int n_in,
                              void* d_out, int out_size) {
    const float* x  = (const float*)d_in[0];
    const float* Wq = (const float*)d_in[1];
    const float* bq = (const float*)d_in[2];
    const float* Wk = (const float*)d_in[3];
    const float* bk = (const float*)d_in[4];
    const float* Wv = (const float*)d_in[5];
    const float* bv = (const float*)d_in[6];
    // d_in[7] (tw): constant along softmax axis (heads) -> cancels; unused.
    (void)in_sizes; (void)n_in; (void)out_size;

    cudaFuncSetAttribute(qkv_gemm_kernel,
                         cudaFuncAttributeMaxDynamicSharedMemorySize, SMEM_BYTES);

    round_x_kernel<<<256, 256>>>((const float4*)x);
    qkv_gemm_kernel<<<dim3(F_OUT / MT, 3), 128, SMEM_BYTES>>>(Wq, bq, Wk, bk, Wv, bv);
    attn_z_kernel<<<dim3(32, 4), 256>>>();
    attn_o_kernel<<<dim3(64, 32), 256>>>((float*)d_out);
}